// round 16
// baseline (speedup 1.0000x reference)
#include <cuda_runtime.h>
#include <cuda_bf16.h>
#include <cuda_fp16.h>
#include <math.h>
#include <stdint.h>

#define NODES_MAX 100000
#define EDGES_MAX 1600000
#define D 128
#define H 8
#define F 512

// ---------------- scratch (static device globals; no allocation allowed) ----
__device__ __half g_feat16[NODES_MAX * D];
__device__ __nv_bfloat16 g_q16[NODES_MAX * D];
__device__ __nv_bfloat16 g_kv[NODES_MAX * 2 * D];  // interleaved k/v per 4-elem chunk
__device__ float g_rstln[NODES_MAX * D];
__device__ __half g_rstln16[NODES_MAX * D];
// fp16 transposed weights [N][K]
__device__ __half g_wtq[D * D];
__device__ __half g_wtk[D * D];
__device__ __half g_wtv[D * D];
__device__ __half g_wt1[F * D];
__device__ __half g_wt2[D * F];
// CSR build
__device__ int g_counts[NODES_MAX];
__device__ int g_rowptr[NODES_MAX + 1];
__device__ int g_wp[NODES_MAX];
__device__ int g_srcl[EDGES_MAX];
__device__ int g_bsums[256];

// ---------------- fp16 tensor-core GEMM core, cp.async double-buffered ------
#define TBM 128
#define TBN 128
#define TBK 32
#define STR 40                      // B smem stride in halves (80B rows)
#define OP_BYTES (128 * STR * 2)    // 10240 per operand
#define STAGE (2 * OP_BYTES)        // 20480
#define GEMM_SMEM (2 * STAGE)       // 40960 (qkv)
#define LNSTRIDE 132

// fused FFN smem layout
#define STRA 136                         // A tile stride (halves)
#define STRH 520                         // hb tile stride (halves)
#define FFN_A_BYTES (128 * STRA * 2)     // 34816
#define FFN_B_OFF FFN_A_BYTES            // 2 B stages follow
#define FFN_HB_OFF (FFN_B_OFF + 2 * OP_BYTES)   // 55296
#define FFN_SMEM (FFN_HB_OFF + 128 * STRH * 2)  // 188416

__device__ __forceinline__ void mma_f16(float* c, const uint32_t* a, const uint32_t* b) {
    asm volatile(
        "mma.sync.aligned.m16n8k16.row.col.f32.f16.f16.f32 "
        "{%0,%1,%2,%3}, {%4,%5,%6,%7}, {%8,%9}, {%0,%1,%2,%3};\n"
        : "+f"(c[0]), "+f"(c[1]), "+f"(c[2]), "+f"(c[3])
        : "r"(a[0]), "r"(a[1]), "r"(a[2]), "r"(a[3]), "r"(b[0]), "r"(b[1]));
}

__device__ __forceinline__ void cp16(void* s, const void* g, bool valid) {
    uint32_t sa = (uint32_t)__cvta_generic_to_shared(s);
    int sz = valid ? 16 : 0;
    asm volatile("cp.async.cg.shared.global [%0], [%1], 16, %2;" ::"r"(sa), "l"(g), "r"(sz));
}

// ---------------- qkv GEMM (MODE 1 only: bf16 store, optional kv interleave) --
__device__ __forceinline__ void gemm_qkv_body(const __half* __restrict__ A,
                                              const __half* __restrict__ Bt,
                                              const float* __restrict__ bias,
                                              __nv_bfloat16* __restrict__ Cb, int kvoff,
                                              int M) {
    extern __shared__ char smem[];
    const int tid = threadIdx.x;
    const int lane = tid & 31;
    const int wid = tid >> 5;
    const int wm = wid & 1;
    const int wn = wid >> 1;
    const int tg = lane >> 2;
    const int tc = lane & 3;

    const int row0 = blockIdx.x * TBM;
    const int T = D / TBK;  // 4

    float acc[4][4][4];
#pragma unroll
    for (int mt = 0; mt < 4; mt++)
#pragma unroll
        for (int nt = 0; nt < 4; nt++)
#pragma unroll
            for (int r = 0; r < 4; r++) acc[mt][nt][r] = 0.0f;

    auto fill = [&](int t) {
        char* st = smem + (t & 1) * STAGE;
        char* sb = st + OP_BYTES;
        const int k0 = t * TBK;
#pragma unroll
        for (int p = 0; p < 2; p++) {
            int idx = tid + p * 256;
            int r = idx >> 2, c8 = (idx & 3) * 8;
            int gr = row0 + r;
            cp16(st + r * 80 + c8 * 2, A + (size_t)gr * D + k0 + c8, gr < M);
            cp16(sb + r * 80 + c8 * 2, Bt + (size_t)r * D + k0 + c8, true);
        }
        asm volatile("cp.async.commit_group;");
    };

    fill(0);
    for (int t = 0; t < T; t++) {
        if (t + 1 < T) {
            fill(t + 1);
            asm volatile("cp.async.wait_group 1;");
        } else {
            asm volatile("cp.async.wait_group 0;");
        }
        __syncthreads();
        const char* st = smem + (t & 1) * STAGE;
        const __half* sA = (const __half*)st;
        const __half* sB = (const __half*)(st + OP_BYTES);
#pragma unroll
        for (int ks = 0; ks < 2; ks++) {
            const int kb = ks * 16;
            uint32_t af[4][4], bf[4][2];
#pragma unroll
            for (int mt = 0; mt < 4; mt++) {
                int mrow = wm * 64 + mt * 16;
                af[mt][0] = *(const uint32_t*)&sA[(mrow + tg) * STR + kb + 2 * tc];
                af[mt][1] = *(const uint32_t*)&sA[(mrow + tg + 8) * STR + kb + 2 * tc];
                af[mt][2] = *(const uint32_t*)&sA[(mrow + tg) * STR + kb + 2 * tc + 8];
                af[mt][3] = *(const uint32_t*)&sA[(mrow + tg + 8) * STR + kb + 2 * tc + 8];
            }
#pragma unroll
            for (int nt = 0; nt < 4; nt++) {
                int ncol = wn * 32 + nt * 8 + tg;
                bf[nt][0] = *(const uint32_t*)&sB[ncol * STR + kb + 2 * tc];
                bf[nt][1] = *(const uint32_t*)&sB[ncol * STR + kb + 2 * tc + 8];
            }
#pragma unroll
            for (int mt = 0; mt < 4; mt++)
#pragma unroll
                for (int nt = 0; nt < 4; nt++) mma_f16(acc[mt][nt], af[mt], bf[nt]);
        }
        __syncthreads();
    }

#pragma unroll
    for (int mt = 0; mt < 4; mt++) {
#pragma unroll
        for (int nt = 0; nt < 4; nt++) {
            int gc = wn * 32 + nt * 8 + tc * 2;
            float b0 = bias[gc], b1 = bias[gc + 1];
            float v0 = acc[mt][nt][0] + b0;
            float v1 = acc[mt][nt][1] + b1;
            float v2 = acc[mt][nt][2] + b0;
            float v3 = acc[mt][nt][3] + b1;
            int gr = row0 + wm * 64 + mt * 16 + tg;
            if (kvoff < 0) {
                if (gr < M)
                    *(__nv_bfloat162*)(Cb + (size_t)gr * D + gc) =
                        __floats2bfloat162_rn(v0, v1);
                if (gr + 8 < M)
                    *(__nv_bfloat162*)(Cb + (size_t)(gr + 8) * D + gc) =
                        __floats2bfloat162_rn(v2, v3);
            } else {
                int cc = ((gc >> 2) << 3) + (gc & 3) + kvoff;
                if (gr < M)
                    *(__nv_bfloat162*)(Cb + (size_t)gr * 2 * D + cc) =
                        __floats2bfloat162_rn(v0, v1);
                if (gr + 8 < M)
                    *(__nv_bfloat162*)(Cb + (size_t)(gr + 8) * 2 * D + cc) =
                        __floats2bfloat162_rn(v2, v3);
            }
        }
    }
}

__global__ __launch_bounds__(256, 2) void qkv_gemm(
    const __half* __restrict__ A, const __half* __restrict__ Wtq,
    const __half* __restrict__ Wtk, const __half* __restrict__ Wtv,
    const float* __restrict__ bq, const float* __restrict__ bk,
    const float* __restrict__ bv, __nv_bfloat16* __restrict__ q16,
    __nv_bfloat16* __restrict__ kv, int M) {
    const __half* Bt = (blockIdx.z == 0) ? Wtq : (blockIdx.z == 1) ? Wtk : Wtv;
    const float* bias = (blockIdx.z == 0) ? bq : (blockIdx.z == 1) ? bk : bv;
    __nv_bfloat16* Cb = (blockIdx.z == 0) ? q16 : kv;
    int kvoff = (blockIdx.z == 0) ? -1 : (blockIdx.z == 1) ? 0 : 4;
    gemm_qkv_body(A, Bt, bias, Cb, kvoff, M);
}

// ---------------- fused FFN: W1+PReLU -> smem hb -> W2 + residual + LN2 ------
__global__ __launch_bounds__(256, 1) void ffn_fused(
    const __half* __restrict__ A,    // rstln16 [M][D]
    const __half* __restrict__ Bt1,  // wt1 [F][D]
    const float* __restrict__ b1, const float* __restrict__ alpha,
    const __half* __restrict__ Bt2,  // wt2 [D][F]
    const float* __restrict__ b2, const float* __restrict__ res,
    const float* __restrict__ lng, const float* __restrict__ lnb,
    float* __restrict__ out, int M) {
    extern __shared__ char smem[];
    __half* sA = (__half*)smem;                    // stride STRA
    char* sB0 = smem + FFN_B_OFF;                  // 2 x OP_BYTES
    __half* sHB = (__half*)(smem + FFN_HB_OFF);    // stride STRH

    const int tid = threadIdx.x;
    const int lane = tid & 31;
    const int wid = tid >> 5;
    const int wm = wid & 1;
    const int wn = wid >> 1;
    const int tg = lane >> 2;
    const int tc = lane & 3;
    const int row0 = blockIdx.x * TBM;

    // load A tile (128 x 128 halves) once
#pragma unroll
    for (int p = 0; p < 8; p++) {
        int idx = tid + p * 256;
        int r = idx >> 4, c16 = idx & 15;
        int gr = row0 + r;
        cp16(smem + r * (STRA * 2) + c16 * 16, A + (size_t)gr * D + c16 * 8, gr < M);
    }

    auto fillB = [&](int it) {
        char* sb = sB0 + (it & 1) * OP_BYTES;
        const __half* src;
        size_t rstride;
        if (it < 16) {
            int nc = it >> 2, t = it & 3;
            src = Bt1 + (size_t)(nc * 128) * D + t * 32;
            rstride = D;
        } else {
            int t = it - 16;
            src = Bt2 + (size_t)t * 32;
            rstride = F;
        }
#pragma unroll
        for (int p = 0; p < 2; p++) {
            int idx = tid + p * 256;
            int r = idx >> 2, c8 = (idx & 3) * 8;
            cp16(sb + r * 80 + c8 * 2, src + (size_t)r * rstride + c8, true);
        }
        asm volatile("cp.async.commit_group;");
    };

    fillB(0);  // group 0 = A tile + B0

    float acc[4][4][4];

    for (int it = 0; it < 32; it++) {
        if (it + 1 < 32) {
            fillB(it + 1);
            asm volatile("cp.async.wait_group 1;");
        } else {
            asm volatile("cp.async.wait_group 0;");
        }
        __syncthreads();

        if ((it < 16 && (it & 3) == 0) || it == 16) {
#pragma unroll
            for (int mt = 0; mt < 4; mt++)
#pragma unroll
                for (int nt = 0; nt < 4; nt++)
#pragma unroll
                    for (int r = 0; r < 4; r++) acc[mt][nt][r] = 0.0f;
        }

        const __half* sFA = (it < 16) ? sA : sHB;
        const int strideA = (it < 16) ? STRA : STRH;
        const int kcol = (it < 16) ? (it & 3) * 32 : (it - 16) * 32;
        const __half* sB = (const __half*)(sB0 + (it & 1) * OP_BYTES);

#pragma unroll
        for (int ks = 0; ks < 2; ks++) {
            const int kb = ks * 16;
            uint32_t af[4][4], bf[4][2];
#pragma unroll
            for (int mt = 0; mt < 4; mt++) {
                int mrow = wm * 64 + mt * 16;
                af[mt][0] = *(const uint32_t*)&sFA[(mrow + tg) * strideA + kcol + kb + 2 * tc];
                af[mt][1] =
                    *(const uint32_t*)&sFA[(mrow + tg + 8) * strideA + kcol + kb + 2 * tc];
                af[mt][2] =
                    *(const uint32_t*)&sFA[(mrow + tg) * strideA + kcol + kb + 2 * tc + 8];
                af[mt][3] =
                    *(const uint32_t*)&sFA[(mrow + tg + 8) * strideA + kcol + kb + 2 * tc + 8];
            }
#pragma unroll
            for (int nt = 0; nt < 4; nt++) {
                int ncol = wn * 32 + nt * 8 + tg;
                bf[nt][0] = *(const uint32_t*)&sB[ncol * STR + kb + 2 * tc];
                bf[nt][1] = *(const uint32_t*)&sB[ncol * STR + kb + 2 * tc + 8];
            }
#pragma unroll
            for (int mt = 0; mt < 4; mt++)
#pragma unroll
                for (int nt = 0; nt < 4; nt++) mma_f16(acc[mt][nt], af[mt], bf[nt]);
        }
        __syncthreads();

        if (it < 16 && (it & 3) == 3) {
            // stage-1 epilogue: bias + PReLU -> fp16 into sHB (same rounding as before)
            int nc = it >> 2;
#pragma unroll
            for (int mt = 0; mt < 4; mt++) {
#pragma unroll
                for (int nt = 0; nt < 4; nt++) {
                    int lc = wn * 32 + nt * 8 + tc * 2;
                    int gcol = nc * 128 + lc;
                    float b0 = b1[gcol], bb1 = b1[gcol + 1];
                    float a0 = alpha[gcol], a1 = alpha[gcol + 1];
                    float v0 = acc[mt][nt][0] + b0;
                    float v1 = acc[mt][nt][1] + bb1;
                    float v2 = acc[mt][nt][2] + b0;
                    float v3 = acc[mt][nt][3] + bb1;
                    v0 = v0 > 0.f ? v0 : a0 * v0;
                    v1 = v1 > 0.f ? v1 : a1 * v1;
                    v2 = v2 > 0.f ? v2 : a0 * v2;
                    v3 = v3 > 0.f ? v3 : a1 * v3;
                    int lr = wm * 64 + mt * 16 + tg;
                    *(__half2*)&sHB[lr * STRH + gcol] = __floats2half2_rn(v0, v1);
                    *(__half2*)&sHB[(lr + 8) * STRH + gcol] = __floats2half2_rn(v2, v3);
                }
            }
        }
    }

    // stage-2 epilogue: residual + LN2 (stage over the dead hb region)
    __syncthreads();
    float* se = (float*)sHB;
#pragma unroll
    for (int mt = 0; mt < 4; mt++) {
#pragma unroll
        for (int nt = 0; nt < 4; nt++) {
            int lc = wn * 32 + nt * 8 + tc * 2;
            float b0 = b2[lc], bb1 = b2[lc + 1];
            int lr = wm * 64 + mt * 16 + tg;
            int gr = row0 + lr;
            if (gr < M) {
                float2 rr = *(const float2*)(res + (size_t)gr * D + lc);
                se[lr * LNSTRIDE + lc] = acc[mt][nt][0] + b0 + rr.x;
                se[lr * LNSTRIDE + lc + 1] = acc[mt][nt][1] + bb1 + rr.y;
            }
            if (gr + 8 < M) {
                float2 rr = *(const float2*)(res + (size_t)(gr + 8) * D + lc);
                se[(lr + 8) * LNSTRIDE + lc] = acc[mt][nt][2] + b0 + rr.x;
                se[(lr + 8) * LNSTRIDE + lc + 1] = acc[mt][nt][3] + bb1 + rr.y;
            }
        }
    }
    __syncthreads();
    float4 gv = *(const float4*)(lng + lane * 4);
    float4 bv = *(const float4*)(lnb + lane * 4);
#pragma unroll
    for (int r = 0; r < 16; r++) {
        int lrow = wid * 16 + r;
        int grow = row0 + lrow;
        if (grow >= M) continue;
        float4 vx = *(const float4*)&se[lrow * LNSTRIDE + lane * 4];
        float s = vx.x + vx.y + vx.z + vx.w;
        float s2 = vx.x * vx.x + vx.y * vx.y + vx.z * vx.z + vx.w * vx.w;
#pragma unroll
        for (int o = 16; o > 0; o >>= 1) {
            s += __shfl_xor_sync(0xffffffffu, s, o);
            s2 += __shfl_xor_sync(0xffffffffu, s2, o);
        }
        float mean = s * (1.0f / D);
        float var = s2 * (1.0f / D) - mean * mean;
        float rstd = rsqrtf(var + 1e-5f);
        float4 o;
        o.x = (vx.x - mean) * rstd * gv.x + bv.x;
        o.y = (vx.y - mean) * rstd * gv.y + bv.y;
        o.z = (vx.z - mean) * rstd * gv.z + bv.z;
        o.w = (vx.w - mean) * rstd * gv.w + bv.w;
        *(float4*)(out + (size_t)grow * D + lane * 4) = o;
    }
}

// ---------------- conversions -------------------------------------------------
__global__ void cvt_feat16(const float* __restrict__ in, __half* __restrict__ out, int n) {
    int base = (blockIdx.x * 256 + threadIdx.x) * 8;
    if (base >= n) return;
    float4 a = *(const float4*)(in + base);
    float4 b = *(const float4*)(in + base + 4);
    __half2 h0 = __floats2half2_rn(a.x, a.y), h1 = __floats2half2_rn(a.z, a.w);
    __half2 h2 = __floats2half2_rn(b.x, b.y), h3 = __floats2half2_rn(b.z, b.w);
    *(uint4*)(out + base) =
        make_uint4(*reinterpret_cast<uint32_t*>(&h0), *reinterpret_cast<uint32_t*>(&h1),
                   *reinterpret_cast<uint32_t*>(&h2), *reinterpret_cast<uint32_t*>(&h3));
}

__global__ void cvt_w_all(const float* __restrict__ Wq, const float* __restrict__ Wk,
                          const float* __restrict__ Wv, const float* __restrict__ W1,
                          const float* __restrict__ W2, __half* __restrict__ wtq,
                          __half* __restrict__ wtk, __half* __restrict__ wtv,
                          __half* __restrict__ wt1, __half* __restrict__ wt2) {
    int idx = blockIdx.x * 256 + threadIdx.x;
    const int S = D * D;
    const int SF = F * D;
    const float* in;
    __half* out;
    int K, N, local;
    if (idx < S) {
        in = Wq; out = wtq; K = D; N = D; local = idx;
    } else if (idx < 2 * S) {
        in = Wk; out = wtk; K = D; N = D; local = idx - S;
    } else if (idx < 3 * S) {
        in = Wv; out = wtv; K = D; N = D; local = idx - 2 * S;
    } else if (idx < 3 * S + SF) {
        in = W1; out = wt1; K = D; N = F; local = idx - 3 * S;
    } else if (idx < 3 * S + 2 * SF) {
        in = W2; out = wt2; K = F; N = D; local = idx - 3 * S - SF;
    } else {
        return;
    }
    int n = local / K;
    int k = local - n * K;
    out[local] = __float2half(in[(size_t)k * N + n]);
}

// ---------------- CSR build --------------------------------------------------
__global__ void hist_kernel(const int* __restrict__ dst, int* __restrict__ counts, int E) {
    int i = blockIdx.x * blockDim.x + threadIdx.x;
    if (i < E) atomicAdd(&counts[dst[i]], 1);
}

__global__ void scan1_kernel(const int* __restrict__ counts, int* __restrict__ rowptr,
                             int* __restrict__ bsums, int n) {
    __shared__ int wsum[8];
    int base = blockIdx.x * 1024 + threadIdx.x * 4;
    int lane = threadIdx.x & 31, wid = threadIdx.x >> 5;
    int v[4];
#pragma unroll
    for (int i = 0; i < 4; i++) v[i] = (base + i < n) ? counts[base + i] : 0;
    int t = v[0] + v[1] + v[2] + v[3];
    int sc = t;
#pragma unroll
    for (int o = 1; o < 32; o <<= 1) {
        int x = __shfl_up_sync(0xffffffffu, sc, o);
        if (lane >= o) sc += x;
    }
    if (lane == 31) wsum[wid] = sc;
    __syncthreads();
    if (wid == 0) {
        int ws = (lane < 8) ? wsum[lane] : 0;
#pragma unroll
        for (int o = 1; o < 8; o <<= 1) {
            int x = __shfl_up_sync(0xffffffffu, ws, o);
            if (lane >= o) ws += x;
        }
        if (lane < 8) wsum[lane] = ws;
    }
    __syncthreads();
    int run = sc - t + (wid > 0 ? wsum[wid - 1] : 0);
#pragma unroll
    for (int i = 0; i < 4; i++) {
        if (base + i < n) rowptr[base + i] = run;
        run += v[i];
    }
    if (threadIdx.x == 0) bsums[blockIdx.x] = wsum[7];
}

__global__ void scan2_kernel(int* __restrict__ bsums, int nb) {
    if (threadIdx.x == 0 && blockIdx.x == 0) {
        int run = 0;
        for (int i = 0; i < nb; i++) {
            int t = bsums[i];
            bsums[i] = run;
            run += t;
        }
    }
}

__global__ void scan3_kernel(int* __restrict__ rowptr, int* __restrict__ wp,
                             const int* __restrict__ bsums, int n, int E) {
    int i = blockIdx.x * blockDim.x + threadIdx.x;
    if (i < n) {
        int v = rowptr[i] + bsums[i >> 10];
        rowptr[i] = v;
        wp[i] = v;
    }
    if (i == 0) rowptr[n] = E;
}

__global__ void fill_kernel(const int* __restrict__ src, const int* __restrict__ dst,
                            int* __restrict__ wp, int* __restrict__ srcl, int E) {
    int i = blockIdx.x * blockDim.x + threadIdx.x;
    if (i >= E) return;
    int pos = atomicAdd(&wp[dst[i]], 1);
    srcl[pos] = src[i];
}

// ---------------- fused per-node attention + LN1 ----------------------------
__device__ __forceinline__ float2 bf2f(uint32_t u) {
    return __bfloat1622float2(*reinterpret_cast<__nv_bfloat162*>(&u));
}

__global__ __launch_bounds__(256) void node_attn_ln(
    const __nv_bfloat16* __restrict__ q, const __nv_bfloat16* __restrict__ kv,
    const int* __restrict__ rowptr, const int* __restrict__ srcl,
    const float* __restrict__ feat, const float* __restrict__ g,
    const float* __restrict__ b, float* __restrict__ out, __half* __restrict__ out16,
    int n) {
    int node = blockIdx.x * 8 + (threadIdx.x >> 5);
    if (node >= n) return;
    int lane = threadIdx.x & 31;

    uint2 qraw = *(const uint2*)(q + (size_t)node * D + lane * 4);
    float2 q0 = bf2f(qraw.x);
    float2 q1 = bf2f(qraw.y);

    int start = rowptr[node], end = rowptr[node + 1];

    float a0 = 0.f, a1 = 0.f, a2 = 0.f, a3 = 0.f, den = 0.f;

    for (int eb = start; eb < end; eb += 32) {
        int me = eb + lane;
        int sid = (me < end) ? srcl[me] : 0;
        int cnt = min(32, end - eb);
        int j = 0;
        for (; j + 4 <= cnt; j += 4) {
            int s0 = __shfl_sync(0xffffffffu, sid, j);
            int s1 = __shfl_sync(0xffffffffu, sid, j + 1);
            int s2 = __shfl_sync(0xffffffffu, sid, j + 2);
            int s3 = __shfl_sync(0xffffffffu, sid, j + 3);
            uint4 x0 = *(const uint4*)(kv + (size_t)s0 * 2 * D + lane * 8);
            uint4 x1 = *(const uint4*)(kv + (size_t)s1 * 2 * D + lane * 8);
            uint4 x2 = *(const uint4*)(kv + (size_t)s2 * 2 * D + lane * 8);
            uint4 x3 = *(const uint4*)(kv + (size_t)s3 * 2 * D + lane * 8);
            float2 ka, kb2;
            float p0, p1, p2, p3;
            ka = bf2f(x0.x); kb2 = bf2f(x0.y);
            p0 = ka.x * q0.x + ka.y * q0.y + kb2.x * q1.x + kb2.y * q1.y;
            ka = bf2f(x1.x); kb2 = bf2f(x1.y);
            p1 = ka.x * q0.x + ka.y * q0.y + kb2.x * q1.x + kb2.y * q1.y;
            ka = bf2f(x2.x); kb2 = bf2f(x2.y);
            p2 = ka.x * q0.x + ka.y * q0.y + kb2.x * q1.x + kb2.y * q1.y;
            ka = bf2f(x3.x); kb2 = bf2f(x3.y);
            p3 = ka.x * q0.x + ka.y * q0.y + kb2.x * q1.x + kb2.y * q1.y;
            p0 += __shfl_xor_sync(0xffffffffu, p0, 1);
            p1 += __shfl_xor_sync(0xffffffffu, p1, 1);
            p2 += __shfl_xor_sync(0xffffffffu, p2, 1);
            p3 += __shfl_xor_sync(0xffffffffu, p3, 1);
            p0 += __shfl_xor_sync(0xffffffffu, p0, 2);
            p1 += __shfl_xor_sync(0xffffffffu, p1, 2);
            p2 += __shfl_xor_sync(0xffffffffu, p2, 2);
            p3 += __shfl_xor_sync(0xffffffffu, p3, 2);
            float e0 = __expf(p0 * 0.08838834764831843f);
            float e1 = __expf(p1 * 0.08838834764831843f);
            float e2 = __expf(p2 * 0.08838834764831843f);
            float e3 = __expf(p3 * 0.08838834764831843f);
            den += (e0 + e1) + (e2 + e3);
            float2 va, vb2;
            va = bf2f(x0.z); vb2 = bf2f(x0.w);
            a0 += va.x * e0; a1 += va.y * e0; a2 += vb2.x * e0; a3 += vb2.y * e0;
            va = bf2f(x1.z); vb2 = bf2f(x1.w);
            a0 += va.x * e1; a1 += va.y * e1; a2 += vb2.x * e1; a3 += vb2.y * e1;
            va = bf2f(x2.z); vb2 = bf2f(x2.w);
            a0 += va.x * e2; a1 += va.y * e2; a2 += vb2.x * e2; a3 += vb2.y * e2;
            va = bf2f(x3.z); vb2 = bf2f(x3.w);
            a0 += va.x * e3; a1 += va.y * e3; a2 += vb2.x * e3; a3 += vb2.y * e3;
        }
        for (; j < cnt; j++) {
            int s = __shfl_sync(0xffffffffu, sid, j);
            uint4 x = *(const uint4*)(kv + (size_t)s * 2 * D + lane * 8);
            float2 k0 = bf2f(x.x), k1 = bf2f(x.y);
            float p = k0.x * q0.x + k0.y * q0.y + k1.x * q1.x + k1.y * q1.y;
            p += __shfl_xor_sync(0xffffffffu, p, 1);
            p += __shfl_xor_sync(0xffffffffu, p, 2);
            float ex = __expf(p * 0.08838834764831843f);
            den += ex;
            float2 v0 = bf2f(x.z), v1 = bf2f(x.w);
            a0 += v0.x * ex;
            a1 += v0.y * ex;
            a2 += v1.x * ex;
            a3 += v1.y * ex;
        }
    }

    float inv = den > 0.f ? 1.0f / den : 0.0f;
    float4 fv = *(const float4*)(feat + (size_t)node * D + lane * 4);
    float r0 = a0 * inv + fv.x;
    float r1 = a1 * inv + fv.y;
    float r2 = a2 * inv + fv.z;
    float r3 = a3 * inv + fv.w;

    float s = r0 + r1 + r2 + r3;
    float s2 = r0 * r0 + r1 * r1 + r2 * r2 + r3 * r3;
#pragma unroll
    for (int o = 16; o > 0; o >>= 1) {
        s += __shfl_xor_sync(0xffffffffu, s, o);
        s2 += __shfl_xor_sync(0xffffffffu, s2, o);
    }
    float mean = s * (1.0f / D);
    float var = s2 * (1.0f / D) - mean * mean;
    float rstd = rsqrtf(var + 1e-5f);
    float4 gv = *(const float4*)(g + lane * 4);
    float4 bv = *(const float4*)(b + lane * 4);
    float4 o;
    o.x = (r0 - mean) * rstd * gv.x + bv.x;
    o.y = (r1 - mean) * rstd * gv.y + bv.y;
    o.z = (r2 - mean) * rstd * gv.z + bv.z;
    o.w = (r3 - mean) * rstd * gv.w + bv.w;
    *(float4*)(out + (size_t)node * D + lane * 4) = o;
    __half2 h0 = __floats2half2_rn(o.x, o.y);
    __half2 h1 = __floats2half2_rn(o.z, o.w);
    uint2 hp =
        make_uint2(*reinterpret_cast<uint32_t*>(&h0), *reinterpret_cast<uint32_t*>(&h1));
    *(uint2*)(out16 + (size_t)node * D + lane * 4) = hp;
}

// ---------------- launch ----------------------------------------------------
extern "C" void kernel_launch(void* const* d_in, const int* in_sizes, int n_in,
                              void* d_out, int out_size) {
    const float* feat = (const float*)d_in[0];
    const int* src = (const int*)d_in[1];
    const int* dst = (const int*)d_in[2];
    const float* Wq = (const float*)d_in[3];
    const float* bq = (const float*)d_in[4];
    const float* Wk = (const float*)d_in[5];
    const float* bk = (const float*)d_in[6];
    const float* Wv = (const float*)d_in[7];
    const float* bv = (const float*)d_in[8];
    const float* ln_g = (const float*)d_in[9];
    const float* ln_b = (const float*)d_in[10];
    const float* W1 = (const float*)d_in[11];
    const float* b1 = (const float*)d_in[12];
    const float* alpha = (const float*)d_in[13];
    const float* W2 = (const float*)d_in[14];
    const float* b2 = (const float*)d_in[15];

    const int N = in_sizes[0] / D;
    const int E = in_sizes[1];

    __nv_bfloat16 *q16, *kv;
    __half *feat16, *rstln16, *wtq, *wtk, *wtv, *wt1, *wt2;
    float* rstln;
    int *counts, *rowptr, *wp, *srcl, *bsums;
    cudaGetSymbolAddress((void**)&feat16, g_feat16);
    cudaGetSymbolAddress((void**)&q16, g_q16);
    cudaGetSymbolAddress((void**)&kv, g_kv);
    cudaGetSymbolAddress((void**)&rstln, g_rstln);
    cudaGetSymbolAddress((void**)&rstln16, g_rstln16);
    cudaGetSymbolAddress((void**)&wtq, g_wtq);
    cudaGetSymbolAddress((void**)&wtk, g_wtk);
    cudaGetSymbolAddress((void**)&wtv, g_wtv);
    cudaGetSymbolAddress((void**)&wt1, g_wt1);
    cudaGetSymbolAddress((void**)&wt2, g_wt2);
    cudaGetSymbolAddress((void**)&counts, g_counts);
    cudaGetSymbolAddress((void**)&rowptr, g_rowptr);
    cudaGetSymbolAddress((void**)&wp, g_wp);
    cudaGetSymbolAddress((void**)&srcl, g_srcl);
    cudaGetSymbolAddress((void**)&bsums, g_bsums);

    static cudaStream_t s1 = nullptr;
    static cudaEvent_t evFork = nullptr, evCsr = nullptr;
    static int attr_set = 0;
    if (!attr_set) {
        cudaFuncSetAttribute(qkv_gemm, cudaFuncAttributeMaxDynamicSharedMemorySize,
                             GEMM_SMEM);
        cudaFuncSetAttribute(ffn_fused, cudaFuncAttributeMaxDynamicSharedMemorySize,
                             FFN_SMEM);
        cudaStreamCreateWithFlags(&s1, cudaStreamNonBlocking);
        cudaEventCreateWithFlags(&evFork, cudaEventDisableTiming);
        cudaEventCreateWithFlags(&evCsr, cudaEventDisableTiming);
        attr_set = 1;
    }

    const int mgrid = (N + TBM - 1) / TBM;
    const int nb = (N + 1023) / 1024;
    const int wtot = 3 * D * D + 2 * F * D;

    // ---- fork: CSR build on side stream, overlapped with conversions + qkv
    cudaEventRecord(evFork, 0);
    cudaStreamWaitEvent(s1, evFork, 0);
    cudaMemsetAsync(counts, 0, (size_t)N * sizeof(int), s1);
    hist_kernel<<<(E + 255) / 256, 256, 0, s1>>>(dst, counts, E);
    scan1_kernel<<<nb, 256, 0, s1>>>(counts, rowptr, bsums, N);
    scan2_kernel<<<1, 32, 0, s1>>>(bsums, nb);
    scan3_kernel<<<(N + 255) / 256, 256, 0, s1>>>(rowptr, wp, bsums, N, E);
    fill_kernel<<<(E + 255) / 256, 256, 0, s1>>>(src, dst, wp, srcl, E);
    cudaEventRecord(evCsr, s1);

    // ---- main stream: conversions then qkv
    cvt_feat16<<<(N * D / 8 + 255) / 256, 256>>>(feat, feat16, N * D);
    cvt_w_all<<<(wtot + 255) / 256, 256>>>(Wq, Wk, Wv, W1, W2, wtq, wtk, wtv, wt1, wt2);

    qkv_gemm<<<dim3(mgrid, 1, 3), 256, GEMM_SMEM>>>(feat16, wtq, wtk, wtv, bq, bk, bv, q16,
                                                    kv, N);

    // ---- join: node_attn needs CSR
    cudaStreamWaitEvent(0, evCsr, 0);
    node_attn_ln<<<(N + 7) / 8, 256>>>(q16, kv, rowptr, srcl, feat, ln_g, ln_b, rstln,
                                       rstln16, N);

    // ---- fused FFN: W1+PReLU -> smem -> W2 + residual + LN2 -> final output
    ffn_fused<<<mgrid, 256, FFN_SMEM>>>(rstln16, wt1, b1, alpha, wt2, b2, rstln, ln_g, ln_b,
                                        (float*)d_out, N);
}

// round 17
// speedup vs baseline: 1.0650x; 1.0650x over previous
#include <cuda_runtime.h>
#include <cuda_bf16.h>
#include <cuda_fp16.h>
#include <math.h>
#include <stdint.h>

#define NODES_MAX 100000
#define EDGES_MAX 1600000
#define D 128
#define H 8
#define F 512

// ---------------- scratch (static device globals; no allocation allowed) ----
__device__ __half g_feat16[NODES_MAX * D];
__device__ __nv_bfloat16 g_q16[NODES_MAX * D];
__device__ __nv_bfloat16 g_kv[NODES_MAX * 2 * D];  // interleaved k/v per 4-elem chunk
__device__ float g_rstln[NODES_MAX * D];
__device__ __half g_rstln16[NODES_MAX * D];
__device__ __half g_h16[NODES_MAX * F];
// fp16 transposed weights [N][K]
__device__ __half g_wtq[D * D];
__device__ __half g_wtk[D * D];
__device__ __half g_wtv[D * D];
__device__ __half g_wt1[F * D];
__device__ __half g_wt2[D * F];
// CSR build
__device__ int g_counts[NODES_MAX];
__device__ int g_rowptr[NODES_MAX + 1];
__device__ int g_wp[NODES_MAX];
__device__ int g_srcl[EDGES_MAX];
__device__ int g_bsums[256];

// ---------------- fp16 tensor-core GEMM core, cp.async double-buffered ------
#define TBM 128
#define TBN 128
#define TBK 32
#define STR 40                      // B smem stride in halves (80B rows)
#define OP_BYTES (128 * STR * 2)    // 10240 per operand
#define STAGE (2 * OP_BYTES)        // 20480
#define GEMM_SMEM (2 * STAGE)       // 40960 (w1/w2)
#define LNSTRIDE 132
#define W2_SMEM (128 * LNSTRIDE * 4)  // 67584 (LN staging)

// merged qkv smem: resident A tile + 2-stage B buffer
#define STRA 136
#define QKV_A_BYTES (128 * STRA * 2)          // 34816
#define QKV_SMEM (QKV_A_BYTES + 2 * OP_BYTES) // 55296

__device__ __forceinline__ void mma_f16(float* c, const uint32_t* a, const uint32_t* b) {
    asm volatile(
        "mma.sync.aligned.m16n8k16.row.col.f32.f16.f16.f32 "
        "{%0,%1,%2,%3}, {%4,%5,%6,%7}, {%8,%9}, {%0,%1,%2,%3};\n"
        : "+f"(c[0]), "+f"(c[1]), "+f"(c[2]), "+f"(c[3])
        : "r"(a[0]), "r"(a[1]), "r"(a[2]), "r"(a[3]), "r"(b[0]), "r"(b[1]));
}

__device__ __forceinline__ void cp16(void* s, const void* g, bool valid) {
    uint32_t sa = (uint32_t)__cvta_generic_to_shared(s);
    int sz = valid ? 16 : 0;
    asm volatile("cp.async.cg.shared.global [%0], [%1], 16, %2;" ::"r"(sa), "l"(g), "r"(sz));
}

// ---------------- merged qkv: A resident, 3 weights x 4 K-tiles --------------
__global__ __launch_bounds__(256, 2) void qkv_merged(
    const __half* __restrict__ A, const __half* __restrict__ Wtq,
    const __half* __restrict__ Wtk, const __half* __restrict__ Wtv,
    const float* __restrict__ bq, const float* __restrict__ bk,
    const float* __restrict__ bv, __nv_bfloat16* __restrict__ q16,
    __nv_bfloat16* __restrict__ kv, int M) {
    extern __shared__ char smem[];
    __half* sA = (__half*)smem;         // stride STRA
    char* sB0 = smem + QKV_A_BYTES;     // 2 x OP_BYTES

    const int tid = threadIdx.x;
    const int lane = tid & 31;
    const int wid = tid >> 5;
    const int wm = wid & 1;
    const int wn = wid >> 1;
    const int tg = lane >> 2;
    const int tc = lane & 3;
    const int row0 = blockIdx.x * TBM;

    const __half* Ws[3] = {Wtq, Wtk, Wtv};

    // A tile load (once): 128 rows x 128 halves
#pragma unroll
    for (int p = 0; p < 8; p++) {
        int idx = tid + p * 256;
        int r = idx >> 4, c16 = idx & 15;
        int gr = row0 + r;
        cp16(smem + r * (STRA * 2) + c16 * 16, A + (size_t)gr * D + c16 * 8, gr < M);
    }

    auto fillB = [&](int it) {
        char* sb = sB0 + (it & 1) * OP_BYTES;
        const __half* src = Ws[it >> 2] + (it & 3) * 32;
#pragma unroll
        for (int p = 0; p < 2; p++) {
            int idx = tid + p * 256;
            int r = idx >> 2, c8 = (idx & 3) * 8;
            cp16(sb + r * 80 + c8 * 2, src + (size_t)r * D + c8, true);
        }
        asm volatile("cp.async.commit_group;");
    };

    fillB(0);  // group 0 = A + B0

    float acc[4][4][4];

    for (int it = 0; it < 12; it++) {
        if (it + 1 < 12) {
            fillB(it + 1);
            asm volatile("cp.async.wait_group 1;");
        } else {
            asm volatile("cp.async.wait_group 0;");
        }
        __syncthreads();

        if ((it & 3) == 0) {
#pragma unroll
            for (int mt = 0; mt < 4; mt++)
#pragma unroll
                for (int nt = 0; nt < 4; nt++)
#pragma unroll
                    for (int r = 0; r < 4; r++) acc[mt][nt][r] = 0.0f;
        }

        const int kcol = (it & 3) * 32;
        const __half* sB = (const __half*)(sB0 + (it & 1) * OP_BYTES);

#pragma unroll
        for (int ks = 0; ks < 2; ks++) {
            const int kb = ks * 16;
            uint32_t af[4][4], bf[4][2];
#pragma unroll
            for (int mt = 0; mt < 4; mt++) {
                int mrow = wm * 64 + mt * 16;
                af[mt][0] = *(const uint32_t*)&sA[(mrow + tg) * STRA + kcol + kb + 2 * tc];
                af[mt][1] =
                    *(const uint32_t*)&sA[(mrow + tg + 8) * STRA + kcol + kb + 2 * tc];
                af[mt][2] =
                    *(const uint32_t*)&sA[(mrow + tg) * STRA + kcol + kb + 2 * tc + 8];
                af[mt][3] =
                    *(const uint32_t*)&sA[(mrow + tg + 8) * STRA + kcol + kb + 2 * tc + 8];
            }
#pragma unroll
            for (int nt = 0; nt < 4; nt++) {
                int ncol = wn * 32 + nt * 8 + tg;
                bf[nt][0] = *(const uint32_t*)&sB[ncol * STR + kb + 2 * tc];
                bf[nt][1] = *(const uint32_t*)&sB[ncol * STR + kb + 2 * tc + 8];
            }
#pragma unroll
            for (int mt = 0; mt < 4; mt++)
#pragma unroll
                for (int nt = 0; nt < 4; nt++) mma_f16(acc[mt][nt], af[mt], bf[nt]);
        }
        __syncthreads();

        if ((it & 3) == 3) {
            int z = it >> 2;
            const float* bias = (z == 0) ? bq : (z == 1) ? bk : bv;
            __nv_bfloat16* Cb = (z == 0) ? q16 : kv;
            int kvoff = (z == 0) ? -1 : (z == 1) ? 0 : 4;
#pragma unroll
            for (int mt = 0; mt < 4; mt++) {
#pragma unroll
                for (int nt = 0; nt < 4; nt++) {
                    int gc = wn * 32 + nt * 8 + tc * 2;
                    float b0 = bias[gc], b1 = bias[gc + 1];
                    float v0 = acc[mt][nt][0] + b0;
                    float v1 = acc[mt][nt][1] + b1;
                    float v2 = acc[mt][nt][2] + b0;
                    float v3 = acc[mt][nt][3] + b1;
                    int gr = row0 + wm * 64 + mt * 16 + tg;
                    if (kvoff < 0) {
                        if (gr < M)
                            *(__nv_bfloat162*)(Cb + (size_t)gr * D + gc) =
                                __floats2bfloat162_rn(v0, v1);
                        if (gr + 8 < M)
                            *(__nv_bfloat162*)(Cb + (size_t)(gr + 8) * D + gc) =
                                __floats2bfloat162_rn(v2, v3);
                    } else {
                        int cc = ((gc >> 2) << 3) + (gc & 3) + kvoff;
                        if (gr < M)
                            *(__nv_bfloat162*)(Cb + (size_t)gr * 2 * D + cc) =
                                __floats2bfloat162_rn(v0, v1);
                        if (gr + 8 < M)
                            *(__nv_bfloat162*)(Cb + (size_t)(gr + 8) * 2 * D + cc) =
                                __floats2bfloat162_rn(v2, v3);
                    }
                }
            }
        }
    }
}

// ---------------- generic fp16 GEMM (w1 / w2+LN) ----------------------------
// MODE: 0 = fp16 store (+PReLU), 2 = fused residual+LayerNorm (fp32 out)
template <int MODE, bool PRELU>
__device__ __forceinline__ void gemm_body(const __half* __restrict__ A,
                                          const __half* __restrict__ Bt,
                                          const float* __restrict__ bias,
                                          const float* __restrict__ alpha,
                                          float* __restrict__ C, __half* __restrict__ Ch,
                                          const float* __restrict__ res,
                                          const float* __restrict__ lng,
                                          const float* __restrict__ lnb, int M, int N,
                                          int K) {
    extern __shared__ char smem[];
    const int tid = threadIdx.x;
    const int lane = tid & 31;
    const int wid = tid >> 5;
    const int wm = wid & 1;
    const int wn = wid >> 1;
    const int tg = lane >> 2;
    const int tc = lane & 3;

    const int row0 = blockIdx.x * TBM;
    const int col0 = blockIdx.y * TBN;
    const int T = K / TBK;

    float acc[4][4][4];
#pragma unroll
    for (int mt = 0; mt < 4; mt++)
#pragma unroll
        for (int nt = 0; nt < 4; nt++)
#pragma unroll
            for (int r = 0; r < 4; r++) acc[mt][nt][r] = 0.0f;

    auto fill = [&](int t) {
        char* st = smem + (t & 1) * STAGE;
        char* sb = st + OP_BYTES;
        const int k0 = t * TBK;
#pragma unroll
        for (int p = 0; p < 2; p++) {
            int idx = tid + p * 256;
            int r = idx >> 2, c8 = (idx & 3) * 8;
            int gr = row0 + r;
            cp16(st + r * 80 + c8 * 2, A + (size_t)gr * K + k0 + c8, gr < M);
            cp16(sb + r * 80 + c8 * 2, Bt + (size_t)(col0 + r) * K + k0 + c8, true);
        }
        asm volatile("cp.async.commit_group;");
    };

    fill(0);

    for (int t = 0; t < T; t++) {
        if (t + 1 < T) {
            fill(t + 1);
            asm volatile("cp.async.wait_group 1;");
        } else {
            asm volatile("cp.async.wait_group 0;");
        }
        __syncthreads();

        const char* st = smem + (t & 1) * STAGE;
        const __half* sA = (const __half*)st;
        const __half* sB = (const __half*)(st + OP_BYTES);

#pragma unroll
        for (int ks = 0; ks < 2; ks++) {
            const int kb = ks * 16;
            uint32_t af[4][4], bf[4][2];
#pragma unroll
            for (int mt = 0; mt < 4; mt++) {
                int mrow = wm * 64 + mt * 16;
                af[mt][0] = *(const uint32_t*)&sA[(mrow + tg) * STR + kb + 2 * tc];
                af[mt][1] = *(const uint32_t*)&sA[(mrow + tg + 8) * STR + kb + 2 * tc];
                af[mt][2] = *(const uint32_t*)&sA[(mrow + tg) * STR + kb + 2 * tc + 8];
                af[mt][3] = *(const uint32_t*)&sA[(mrow + tg + 8) * STR + kb + 2 * tc + 8];
            }
#pragma unroll
            for (int nt = 0; nt < 4; nt++) {
                int ncol = wn * 32 + nt * 8 + tg;
                bf[nt][0] = *(const uint32_t*)&sB[ncol * STR + kb + 2 * tc];
                bf[nt][1] = *(const uint32_t*)&sB[ncol * STR + kb + 2 * tc + 8];
            }
#pragma unroll
            for (int mt = 0; mt < 4; mt++)
#pragma unroll
                for (int nt = 0; nt < 4; nt++) mma_f16(acc[mt][nt], af[mt], bf[nt]);
        }
        __syncthreads();
    }

    if (MODE == 2) {
        float* se = (float*)smem;
#pragma unroll
        for (int mt = 0; mt < 4; mt++) {
#pragma unroll
            for (int nt = 0; nt < 4; nt++) {
                int lc = wn * 32 + nt * 8 + tc * 2;
                int gc = col0 + lc;
                float b0 = bias[gc], b1 = bias[gc + 1];
                int lr = wm * 64 + mt * 16 + tg;
                int gr = row0 + lr;
                if (gr < M) {
                    float2 rr = *(const float2*)(res + (size_t)gr * N + gc);
                    se[lr * LNSTRIDE + lc] = acc[mt][nt][0] + b0 + rr.x;
                    se[lr * LNSTRIDE + lc + 1] = acc[mt][nt][1] + b1 + rr.y;
                }
                if (gr + 8 < M) {
                    float2 rr = *(const float2*)(res + (size_t)(gr + 8) * N + gc);
                    se[(lr + 8) * LNSTRIDE + lc] = acc[mt][nt][2] + b0 + rr.x;
                    se[(lr + 8) * LNSTRIDE + lc + 1] = acc[mt][nt][3] + b1 + rr.y;
                }
            }
        }
        __syncthreads();
        float4 gv = *(const float4*)(lng + lane * 4);
        float4 bv = *(const float4*)(lnb + lane * 4);
#pragma unroll
        for (int r = 0; r < 16; r++) {
            int lrow = wid * 16 + r;
            int grow = row0 + lrow;
            if (grow >= M) continue;
            float4 vx = *(const float4*)&se[lrow * LNSTRIDE + lane * 4];
            float s = vx.x + vx.y + vx.z + vx.w;
            float s2 = vx.x * vx.x + vx.y * vx.y + vx.z * vx.z + vx.w * vx.w;
#pragma unroll
            for (int o = 16; o > 0; o >>= 1) {
                s += __shfl_xor_sync(0xffffffffu, s, o);
                s2 += __shfl_xor_sync(0xffffffffu, s2, o);
            }
            float mean = s * (1.0f / D);
            float var = s2 * (1.0f / D) - mean * mean;
            float rstd = rsqrtf(var + 1e-5f);
            float4 o;
            o.x = (vx.x - mean) * rstd * gv.x + bv.x;
            o.y = (vx.y - mean) * rstd * gv.y + bv.y;
            o.z = (vx.z - mean) * rstd * gv.z + bv.z;
            o.w = (vx.w - mean) * rstd * gv.w + bv.w;
            *(float4*)(C + (size_t)grow * N + lane * 4) = o;
        }
        return;
    }

#pragma unroll
    for (int mt = 0; mt < 4; mt++) {
#pragma unroll
        for (int nt = 0; nt < 4; nt++) {
            int gc = col0 + wn * 32 + nt * 8 + tc * 2;
            float b0 = bias[gc], b1 = bias[gc + 1];
            float v0 = acc[mt][nt][0] + b0;
            float v1 = acc[mt][nt][1] + b1;
            float v2 = acc[mt][nt][2] + b0;
            float v3 = acc[mt][nt][3] + b1;
            if (PRELU) {
                float a0 = alpha[gc], a1 = alpha[gc + 1];
                v0 = v0 > 0.f ? v0 : a0 * v0;
                v1 = v1 > 0.f ? v1 : a1 * v1;
                v2 = v2 > 0.f ? v2 : a0 * v2;
                v3 = v3 > 0.f ? v3 : a1 * v3;
            }
            int gr = row0 + wm * 64 + mt * 16 + tg;
            if (gr < M) *(__half2*)(Ch + (size_t)gr * N + gc) = __floats2half2_rn(v0, v1);
            if (gr + 8 < M)
                *(__half2*)(Ch + (size_t)(gr + 8) * N + gc) = __floats2half2_rn(v2, v3);
        }
    }
}

// W1: fp16 A (rstln16) -> fp16 out (hb16) + PReLU
__global__ __launch_bounds__(256, 2) void w1_gemm(
    const __half* __restrict__ A, const __half* __restrict__ Bt,
    const float* __restrict__ bias, const float* __restrict__ alpha,
    __half* __restrict__ C, int M) {
    gemm_body<0, true>(A, Bt, bias, alpha, nullptr, C, nullptr, nullptr, nullptr, M, F, D);
}

// W2: fp16 A (hb16) + residual(fp32) + LN2 -> final output
__global__ __launch_bounds__(256, 2) void w2_ln_gemm(
    const __half* __restrict__ A, const __half* __restrict__ Bt,
    const float* __restrict__ bias, const float* __restrict__ res,
    const float* __restrict__ lng, const float* __restrict__ lnb, float* __restrict__ out,
    int M) {
    gemm_body<2, false>(A, Bt, bias, nullptr, out, nullptr, res, lng, lnb, M, D, F);
}

// ---------------- conversions -------------------------------------------------
__global__ void cvt_feat16(const float* __restrict__ in, __half* __restrict__ out, int n) {
    int base = (blockIdx.x * 256 + threadIdx.x) * 8;
    if (base >= n) return;
    float4 a = *(const float4*)(in + base);
    float4 b = *(const float4*)(in + base + 4);
    __half2 h0 = __floats2half2_rn(a.x, a.y), h1 = __floats2half2_rn(a.z, a.w);
    __half2 h2 = __floats2half2_rn(b.x, b.y), h3 = __floats2half2_rn(b.z, b.w);
    *(uint4*)(out + base) =
        make_uint4(*reinterpret_cast<uint32_t*>(&h0), *reinterpret_cast<uint32_t*>(&h1),
                   *reinterpret_cast<uint32_t*>(&h2), *reinterpret_cast<uint32_t*>(&h3));
}

__global__ void cvt_w_all(const float* __restrict__ Wq, const float* __restrict__ Wk,
                          const float* __restrict__ Wv, const float* __restrict__ W1,
                          const float* __restrict__ W2, __half* __restrict__ wtq,
                          __half* __restrict__ wtk, __half* __restrict__ wtv,
                          __half* __restrict__ wt1, __half* __restrict__ wt2) {
    int idx = blockIdx.x * 256 + threadIdx.x;
    const int S = D * D;
    const int SF = F * D;
    const float* in;
    __half* out;
    int K, N, local;
    if (idx < S) {
        in = Wq; out = wtq; K = D; N = D; local = idx;
    } else if (idx < 2 * S) {
        in = Wk; out = wtk; K = D; N = D; local = idx - S;
    } else if (idx < 3 * S) {
        in = Wv; out = wtv; K = D; N = D; local = idx - 2 * S;
    } else if (idx < 3 * S + SF) {
        in = W1; out = wt1; K = D; N = F; local = idx - 3 * S;
    } else if (idx < 3 * S + 2 * SF) {
        in = W2; out = wt2; K = F; N = D; local = idx - 3 * S - SF;
    } else {
        return;
    }
    int n = local / K;
    int k = local - n * K;
    out[local] = __float2half(in[(size_t)k * N + n]);
}

// ---------------- CSR build --------------------------------------------------
__global__ void hist_kernel(const int* __restrict__ dst, int* __restrict__ counts, int E) {
    int i = blockIdx.x * blockDim.x + threadIdx.x;
    if (i < E) atomicAdd(&counts[dst[i]], 1);
}

__global__ void scan1_kernel(const int* __restrict__ counts, int* __restrict__ rowptr,
                             int* __restrict__ bsums, int n) {
    __shared__ int wsum[8];
    int base = blockIdx.x * 1024 + threadIdx.x * 4;
    int lane = threadIdx.x & 31, wid = threadIdx.x >> 5;
    int v[4];
#pragma unroll
    for (int i = 0; i < 4; i++) v[i] = (base + i < n) ? counts[base + i] : 0;
    int t = v[0] + v[1] + v[2] + v[3];
    int sc = t;
#pragma unroll
    for (int o = 1; o < 32; o <<= 1) {
        int x = __shfl_up_sync(0xffffffffu, sc, o);
        if (lane >= o) sc += x;
    }
    if (lane == 31) wsum[wid] = sc;
    __syncthreads();
    if (wid == 0) {
        int ws = (lane < 8) ? wsum[lane] : 0;
#pragma unroll
        for (int o = 1; o < 8; o <<= 1) {
            int x = __shfl_up_sync(0xffffffffu, ws, o);
            if (lane >= o) ws += x;
        }
        if (lane < 8) wsum[lane] = ws;
    }
    __syncthreads();
    int run = sc - t + (wid > 0 ? wsum[wid - 1] : 0);
#pragma unroll
    for (int i = 0; i < 4; i++) {
        if (base + i < n) rowptr[base + i] = run;
        run += v[i];
    }
    if (threadIdx.x == 0) bsums[blockIdx.x] = wsum[7];
}

__global__ void scan2_kernel(int* __restrict__ bsums, int nb) {
    if (threadIdx.x == 0 && blockIdx.x == 0) {
        int run = 0;
        for (int i = 0; i < nb; i++) {
            int t = bsums[i];
            bsums[i] = run;
            run += t;
        }
    }
}

__global__ void scan3_kernel(int* __restrict__ rowptr, int* __restrict__ wp,
                             const int* __restrict__ bsums, int n, int E) {
    int i = blockIdx.x * blockDim.x + threadIdx.x;
    if (i < n) {
        int v = rowptr[i] + bsums[i >> 10];
        rowptr[i] = v;
        wp[i] = v;
    }
    if (i == 0) rowptr[n] = E;
}

__global__ void fill_kernel(const int* __restrict__ src, const int* __restrict__ dst,
                            int* __restrict__ wp, int* __restrict__ srcl, int E) {
    int i = blockIdx.x * blockDim.x + threadIdx.x;
    if (i >= E) return;
    int pos = atomicAdd(&wp[dst[i]], 1);
    srcl[pos] = src[i];
}

// ---------------- fused per-node attention + LN1 ----------------------------
__device__ __forceinline__ float2 bf2f(uint32_t u) {
    return __bfloat1622float2(*reinterpret_cast<__nv_bfloat162*>(&u));
}

__global__ __launch_bounds__(256) void node_attn_ln(
    const __nv_bfloat16* __restrict__ q, const __nv_bfloat16* __restrict__ kv,
    const int* __restrict__ rowptr, const int* __restrict__ srcl,
    const float* __restrict__ feat, const float* __restrict__ g,
    const float* __restrict__ b, float* __restrict__ out, __half* __restrict__ out16,
    int n) {
    int node = blockIdx.x * 8 + (threadIdx.x >> 5);
    if (node >= n) return;
    int lane = threadIdx.x & 31;

    uint2 qraw = *(const uint2*)(q + (size_t)node * D + lane * 4);
    float2 q0 = bf2f(qraw.x);
    float2 q1 = bf2f(qraw.y);

    int start = rowptr[node], end = rowptr[node + 1];

    float a0 = 0.f, a1 = 0.f, a2 = 0.f, a3 = 0.f, den = 0.f;

    for (int eb = start; eb < end; eb += 32) {
        int me = eb + lane;
        int sid = (me < end) ? srcl[me] : 0;
        int cnt = min(32, end - eb);
        int j = 0;
        for (; j + 4 <= cnt; j += 4) {
            int s0 = __shfl_sync(0xffffffffu, sid, j);
            int s1 = __shfl_sync(0xffffffffu, sid, j + 1);
            int s2 = __shfl_sync(0xffffffffu, sid, j + 2);
            int s3 = __shfl_sync(0xffffffffu, sid, j + 3);
            uint4 x0 = *(const uint4*)(kv + (size_t)s0 * 2 * D + lane * 8);
            uint4 x1 = *(const uint4*)(kv + (size_t)s1 * 2 * D + lane * 8);
            uint4 x2 = *(const uint4*)(kv + (size_t)s2 * 2 * D + lane * 8);
            uint4 x3 = *(const uint4*)(kv + (size_t)s3 * 2 * D + lane * 8);
            float2 ka, kb2;
            float p0, p1, p2, p3;
            ka = bf2f(x0.x); kb2 = bf2f(x0.y);
            p0 = ka.x * q0.x + ka.y * q0.y + kb2.x * q1.x + kb2.y * q1.y;
            ka = bf2f(x1.x); kb2 = bf2f(x1.y);
            p1 = ka.x * q0.x + ka.y * q0.y + kb2.x * q1.x + kb2.y * q1.y;
            ka = bf2f(x2.x); kb2 = bf2f(x2.y);
            p2 = ka.x * q0.x + ka.y * q0.y + kb2.x * q1.x + kb2.y * q1.y;
            ka = bf2f(x3.x); kb2 = bf2f(x3.y);
            p3 = ka.x * q0.x + ka.y * q0.y + kb2.x * q1.x + kb2.y * q1.y;
            p0 += __shfl_xor_sync(0xffffffffu, p0, 1);
            p1 += __shfl_xor_sync(0xffffffffu, p1, 1);
            p2 += __shfl_xor_sync(0xffffffffu, p2, 1);
            p3 += __shfl_xor_sync(0xffffffffu, p3, 1);
            p0 += __shfl_xor_sync(0xffffffffu, p0, 2);
            p1 += __shfl_xor_sync(0xffffffffu, p1, 2);
            p2 += __shfl_xor_sync(0xffffffffu, p2, 2);
            p3 += __shfl_xor_sync(0xffffffffu, p3, 2);
            float e0 = __expf(p0 * 0.08838834764831843f);
            float e1 = __expf(p1 * 0.08838834764831843f);
            float e2 = __expf(p2 * 0.08838834764831843f);
            float e3 = __expf(p3 * 0.08838834764831843f);
            den += (e0 + e1) + (e2 + e3);
            float2 va, vb2;
            va = bf2f(x0.z); vb2 = bf2f(x0.w);
            a0 += va.x * e0; a1 += va.y * e0; a2 += vb2.x * e0; a3 += vb2.y * e0;
            va = bf2f(x1.z); vb2 = bf2f(x1.w);
            a0 += va.x * e1; a1 += va.y * e1; a2 += vb2.x * e1; a3 += vb2.y * e1;
            va = bf2f(x2.z); vb2 = bf2f(x2.w);
            a0 += va.x * e2; a1 += va.y * e2; a2 += vb2.x * e2; a3 += vb2.y * e2;
            va = bf2f(x3.z); vb2 = bf2f(x3.w);
            a0 += va.x * e3; a1 += va.y * e3; a2 += vb2.x * e3; a3 += vb2.y * e3;
        }
        for (; j < cnt; j++) {
            int s = __shfl_sync(0xffffffffu, sid, j);
            uint4 x = *(const uint4*)(kv + (size_t)s * 2 * D + lane * 8);
            float2 k0 = bf2f(x.x), k1 = bf2f(x.y);
            float p = k0.x * q0.x + k0.y * q0.y + k1.x * q1.x + k1.y * q1.y;
            p += __shfl_xor_sync(0xffffffffu, p, 1);
            p += __shfl_xor_sync(0xffffffffu, p, 2);
            float ex = __expf(p * 0.08838834764831843f);
            den += ex;
            float2 v0 = bf2f(x.z), v1 = bf2f(x.w);
            a0 += v0.x * ex;
            a1 += v0.y * ex;
            a2 += v1.x * ex;
            a3 += v1.y * ex;
        }
    }

    float inv = den > 0.f ? 1.0f / den : 0.0f;
    float4 fv = *(const float4*)(feat + (size_t)node * D + lane * 4);
    float r0 = a0 * inv + fv.x;
    float r1 = a1 * inv + fv.y;
    float r2 = a2 * inv + fv.z;
    float r3 = a3 * inv + fv.w;

    float s = r0 + r1 + r2 + r3;
    float s2 = r0 * r0 + r1 * r1 + r2 * r2 + r3 * r3;
#pragma unroll
    for (int o = 16; o > 0; o >>= 1) {
        s += __shfl_xor_sync(0xffffffffu, s, o);
        s2 += __shfl_xor_sync(0xffffffffu, s2, o);
    }
    float mean = s * (1.0f / D);
    float var = s2 * (1.0f / D) - mean * mean;
    float rstd = rsqrtf(var + 1e-5f);
    float4 gv = *(const float4*)(g + lane * 4);
    float4 bv = *(const float4*)(b + lane * 4);
    float4 o;
    o.x = (r0 - mean) * rstd * gv.x + bv.x;
    o.y = (r1 - mean) * rstd * gv.y + bv.y;
    o.z = (r2 - mean) * rstd * gv.z + bv.z;
    o.w = (r3 - mean) * rstd * gv.w + bv.w;
    *(float4*)(out + (size_t)node * D + lane * 4) = o;
    __half2 h0 = __floats2half2_rn(o.x, o.y);
    __half2 h1 = __floats2half2_rn(o.z, o.w);
    uint2 hp =
        make_uint2(*reinterpret_cast<uint32_t*>(&h0), *reinterpret_cast<uint32_t*>(&h1));
    *(uint2*)(out16 + (size_t)node * D + lane * 4) = hp;
}

// ---------------- launch ----------------------------------------------------
extern "C" void kernel_launch(void* const* d_in, const int* in_sizes, int n_in,
                              void* d_out, int out_size) {
    const float* feat = (const float*)d_in[0];
    const int* src = (const int*)d_in[1];
    const int* dst = (const int*)d_in[2];
    const float* Wq = (const float*)d_in[3];
    const float* bq = (const float*)d_in[4];
    const float* Wk = (const float*)d_in[5];
    const float* bk = (const float*)d_in[6];
    const float* Wv = (const float*)d_in[7];
    const float* bv = (const float*)d_in[8];
    const float* ln_g = (const float*)d_in[9];
    const float* ln_b = (const float*)d_in[10];
    const float* W1 = (const float*)d_in[11];
    const float* b1 = (const float*)d_in[12];
    const float* alpha = (const float*)d_in[13];
    const float* W2 = (const float*)d_in[14];
    const float* b2 = (const float*)d_in[15];

    const int N = in_sizes[0] / D;
    const int E = in_sizes[1];

    __nv_bfloat16 *q16, *kv;
    __half *feat16, *rstln16, *hb16, *wtq, *wtk, *wtv, *wt1, *wt2;
    float* rstln;
    int *counts, *rowptr, *wp, *srcl, *bsums;
    cudaGetSymbolAddress((void**)&feat16, g_feat16);
    cudaGetSymbolAddress((void**)&q16, g_q16);
    cudaGetSymbolAddress((void**)&kv, g_kv);
    cudaGetSymbolAddress((void**)&rstln, g_rstln);
    cudaGetSymbolAddress((void**)&rstln16, g_rstln16);
    cudaGetSymbolAddress((void**)&hb16, g_h16);
    cudaGetSymbolAddress((void**)&wtq, g_wtq);
    cudaGetSymbolAddress((void**)&wtk, g_wtk);
    cudaGetSymbolAddress((void**)&wtv, g_wtv);
    cudaGetSymbolAddress((void**)&wt1, g_wt1);
    cudaGetSymbolAddress((void**)&wt2, g_wt2);
    cudaGetSymbolAddress((void**)&counts, g_counts);
    cudaGetSymbolAddress((void**)&rowptr, g_rowptr);
    cudaGetSymbolAddress((void**)&wp, g_wp);
    cudaGetSymbolAddress((void**)&srcl, g_srcl);
    cudaGetSymbolAddress((void**)&bsums, g_bsums);

    static cudaStream_t s1 = nullptr;
    static cudaEvent_t evFork = nullptr, evCsr = nullptr, evW = nullptr;
    static int attr_set = 0;
    if (!attr_set) {
        cudaFuncSetAttribute(qkv_merged, cudaFuncAttributeMaxDynamicSharedMemorySize,
                             QKV_SMEM);
        cudaFuncSetAttribute(w1_gemm, cudaFuncAttributeMaxDynamicSharedMemorySize, GEMM_SMEM);
        cudaFuncSetAttribute(w2_ln_gemm, cudaFuncAttributeMaxDynamicSharedMemorySize,
                             W2_SMEM);
        cudaStreamCreateWithFlags(&s1, cudaStreamNonBlocking);
        cudaEventCreateWithFlags(&evFork, cudaEventDisableTiming);
        cudaEventCreateWithFlags(&evCsr, cudaEventDisableTiming);
        cudaEventCreateWithFlags(&evW, cudaEventDisableTiming);
        attr_set = 1;
    }

    const int mgrid = (N + TBM - 1) / TBM;
    const int nb = (N + 1023) / 1024;
    const int wtot = 3 * D * D + 2 * F * D;

    // ---- fork: weight conversion + CSR build on side stream
    cudaEventRecord(evFork, 0);
    cudaStreamWaitEvent(s1, evFork, 0);
    cvt_w_all<<<(wtot + 255) / 256, 256, 0, s1>>>(Wq, Wk, Wv, W1, W2, wtq, wtk, wtv, wt1,
                                                  wt2);
    cudaEventRecord(evW, s1);
    cudaMemsetAsync(counts, 0, (size_t)N * sizeof(int), s1);
    hist_kernel<<<(E + 255) / 256, 256, 0, s1>>>(dst, counts, E);
    scan1_kernel<<<nb, 256, 0, s1>>>(counts, rowptr, bsums, N);
    scan2_kernel<<<1, 32, 0, s1>>>(bsums, nb);
    scan3_kernel<<<(N + 255) / 256, 256, 0, s1>>>(rowptr, wp, bsums, N, E);
    fill_kernel<<<(E + 255) / 256, 256, 0, s1>>>(src, dst, wp, srcl, E);
    cudaEventRecord(evCsr, s1);

    // ---- main stream: feat conversion, then merged qkv (A read once)
    cvt_feat16<<<(N * D / 8 + 255) / 256, 256>>>(feat, feat16, N * D);
    cudaStreamWaitEvent(0, evW, 0);
    qkv_merged<<<mgrid, 256, QKV_SMEM>>>(feat16, wtq, wtk, wtv, bq, bk, bv, q16, kv, N);

    // ---- join: node_attn needs CSR
    cudaStreamWaitEvent(0, evCsr, 0);
    node_attn_ln<<<(N + 7) / 8, 256>>>(q16, kv, rowptr, srcl, feat, ln_g, ln_b, rstln,
                                       rstln16, N);

    // ---- FFN: W1 (fp16, +PReLU), then W2 + residual + LN2 -> final output
    w1_gemm<<<dim3(mgrid, F / TBN), 256, GEMM_SMEM>>>(rstln16, wt1, b1, alpha, hb16, N);
    w2_ln_gemm<<<dim3(mgrid, 1), 256, W2_SMEM>>>(hb16, wt2, b2, rstln, ln_g, ln_b,
                                                 (float*)d_out, N);
}